// round 8
// baseline (speedup 1.0000x reference)
#include <cuda_runtime.h>
#include <cuda_bf16.h>
#include <math.h>
#include <stdint.h>

#define TT 8
#define NNODE 40000
#define FF 256
#define PP 128
#define GG 128
#define HH 128
#define BB 1024
#define NE 640000
#define NNZ (NE + NNODE)

// ------------------------- device scratch -------------------------
__device__ __align__(16) float g_h  [(size_t)NNODE * PP];
__device__ __align__(16) float g_m  [(size_t)NNODE * GG];
__device__ __align__(16) float g_h2 [(size_t)NNODE * GG];
__device__ __align__(16) float g_hc [(size_t)NNODE * GG];
__device__ __align__(16) float g_mc [(size_t)NNODE * GG];
__device__ __align__(16) float g_tgt[(size_t)TT * BB * (2 * GG)];
__device__ __align__(16) float g_gi [(size_t)TT * BB * (3 * HH)];
__device__ __align__(16) float g_gh [(size_t)BB * (3 * HH)];
__device__ __align__(16) float g_gruh[(size_t)BB * HH];
__device__ __align__(16) float g_outs[(size_t)TT * BB * HH];
__device__ __align__(16) float g_val [NNZ];
__device__ __align__(16) float g_dinv[NNODE];
__device__ __align__(16) int   g_col [NNZ];
__device__ __align__(16) int   g_rowptr[NNODE + 1];
__device__ __align__(16) int   g_deg [NNODE];
__device__ __align__(16) int   g_fill[NNODE];
__device__ __align__(16) int   g_src [NE];
__device__ __align__(16) int   g_dst [NE];
__device__ __align__(16) int   g_ti  [BB];
// pruning structures
__device__ __align__(16) int   g_tmask[NNODE];
__device__ __align__(16) int   g_smask[NNODE];
__device__ __align__(16) int   g_snodes[NNODE];
__device__ __align__(16) int   g_sidx [NNODE];
__device__ __align__(16) int   g_tnodes[BB];
__device__ int g_nt;
__device__ int g_ns;
__device__ int g_is64;
// permuted tf32 weights (fragment-linear order)
__device__ __align__(16) uint32_t g_pw  [256 * 128];
__device__ __align__(16) uint32_t g_pw1 [128 * 128];
__device__ __align__(16) uint32_t g_pw2 [128 * 128];
__device__ __align__(16) uint32_t g_pwih[256 * 384];
__device__ __align__(16) uint32_t g_pwhh[128 * 384];

// ------------------------- tf32 helpers -------------------------
__device__ __forceinline__ uint32_t f2tf(float f) {
    uint32_t r;
    asm("cvt.rna.tf32.f32 %0, %1;" : "=r"(r) : "f"(f));
    return r;
}
__device__ __forceinline__ void mma8(float* c, const uint32_t* a, const uint32_t* b) {
    asm volatile(
        "mma.sync.aligned.m16n8k8.row.col.f32.tf32.tf32.f32 "
        "{%0,%1,%2,%3},{%4,%5,%6,%7},{%8,%9},{%0,%1,%2,%3};"
        : "+f"(c[0]), "+f"(c[1]), "+f"(c[2]), "+f"(c[3])
        : "r"(a[0]), "r"(a[1]), "r"(a[2]), "r"(a[3]), "r"(b[0]), "r"(b[1]));
}

// ------------------------- weight permutation to fragment order (verified R5/R6) ----
template<bool TRANS>
__global__ void k_permB(const float* __restrict__ W, uint32_t* __restrict__ out, int K, int N) {
    int i = blockIdx.x * blockDim.x + threadIdx.x;
    if (i >= K * N) return;
    int tmp = i;
    int j = tmp & 1;       tmp >>= 1;
    int lane = tmp & 31;   tmp >>= 5;
    int nt = tmp & 15;     tmp >>= 4;
    int K8 = K >> 3;
    int kg = tmp % K8;
    int nb = tmp / K8;
    int k = kg * 8 + (lane & 3) + 4 * j;
    int n = nb * 128 + nt * 8 + (lane >> 2);
    float v = TRANS ? W[(size_t)n * K + k] : W[(size_t)k * N + n];
    out[i] = f2tf(v);
}

// ------------------------- TF32 GEMM, pipelined -------------------------
// CTA 128x128, 8 warps (warpM 0..3 x32 rows, warpN 0..1 x64 cols).
// B: permuted gmem -> smem panel (64KB per 128-K panel, contiguous copy).
// A: double-buffered 16-K fragment-order smem chunks; LDG prefetch || MMA.
// ASEL: 0 ext, 1 g_h, 2 g_hc, 3 g_tgt, 4 g_gruh ; CSEL: 1 g_h, 2 g_m, 3 g_mc, 4 g_gi, 5 g_gh
// MSEL: 0 param M, 1 g_ns
template<int KTOT, int ASEL, int CSEL, int MSEL, bool RELU, bool BIAS>
__global__ void __launch_bounds__(256) tfgemm(const float* __restrict__ Aext,
                                              const uint32_t* __restrict__ pB,
                                              const float* __restrict__ bias, int Mparam)
{
    extern __shared__ uint32_t sm_[];
    const int BKP = (KTOT < 128) ? KTOT : 128;   // panel K
    const int CPP = BKP / 16;                    // chunks per panel
    const int NCH = KTOT / 16;                   // total chunks
    uint32_t* Bp = sm_;                          // BKP*128 words
    uint32_t* Ad = sm_ + BKP * 128;              // 2 * 2048 words

    int M = (MSEL == 1) ? g_ns : Mparam;
    int rowBase = blockIdx.y * 128;
    if (rowBase >= M) return;

    const float* A;
    if constexpr (ASEL == 1)      A = g_h;
    else if constexpr (ASEL == 2) A = g_hc;
    else if constexpr (ASEL == 3) A = g_tgt;
    else if constexpr (ASEL == 4) A = g_gruh;
    else                          A = Aext;
    float* C;
    if constexpr (CSEL == 1)      C = g_h;
    else if constexpr (CSEL == 2) C = g_m;
    else if constexpr (CSEL == 3) C = g_mc;
    else if constexpr (CSEL == 4) C = g_gi;
    else                          C = g_gh;

    const int N = gridDim.x * 128;
    const int nb = blockIdx.x;
    int tid = threadIdx.x;
    int lane = tid & 31;
    int w = tid >> 5;
    int warpM = w & 3;
    int warpN = w >> 2;

    // A loader indices (verified fragment layout)
    int r_local = tid >> 1;                 // 0..127
    int ksl = tid & 1;
    int rr = r_local & 15;
    int mtg = r_local >> 4;
    int sbase = (mtg * 2 + ksl) * 128;
    int lane4 = (rr & 7) * 4;
    int slot = rr >> 3;
    int grl = rowBase + r_local;
    const float* pa = A + (size_t)(grl < M ? grl : M - 1) * KTOT + ksl * 8;

    float acc[2][8][4];
#pragma unroll
    for (int mt = 0; mt < 2; mt++)
#pragma unroll
        for (int nt = 0; nt < 8; nt++)
#pragma unroll
            for (int q = 0; q < 4; q++) acc[mt][nt][q] = 0.f;

    // stage B panel 0
    {
        const uint4* src = (const uint4*)(pB + (size_t)nb * KTOT * 128);
        uint4* dst = (uint4*)Bp;
#pragma unroll
        for (int i = 0; i < BKP / 8; i++) dst[i * 256 + tid] = src[i * 256 + tid];
    }
    // prologue: stage A chunk 0 into buffer 0
    {
        float4 v0 = *(const float4*)(pa + 0);
        float4 v1 = *(const float4*)(pa + 4);
        uint32_t* b0 = Ad + sbase;
        b0[(lane4 + 0) * 4 + slot] = f2tf(v0.x);
        b0[(lane4 + 1) * 4 + slot] = f2tf(v0.y);
        b0[(lane4 + 2) * 4 + slot] = f2tf(v0.z);
        b0[(lane4 + 3) * 4 + slot] = f2tf(v0.w);
        b0[(lane4 + 0) * 4 + slot + 2] = f2tf(v1.x);
        b0[(lane4 + 1) * 4 + slot + 2] = f2tf(v1.y);
        b0[(lane4 + 2) * 4 + slot + 2] = f2tf(v1.z);
        b0[(lane4 + 3) * 4 + slot + 2] = f2tf(v1.w);
    }
    __syncthreads();

    for (int c = 0; c < NCH; c++) {
        bool haveNext = (c + 1 < NCH);
        float4 v0, v1;
        if (haveNext) {
            v0 = *(const float4*)(pa + (c + 1) * 16);
            v1 = *(const float4*)(pa + (c + 1) * 16 + 4);
        }
        // compute chunk c
        const uint32_t* Ab = Ad + (c & 1) * 2048;
        int kgl0 = (c % CPP) * 2;
#pragma unroll
        for (int ks = 0; ks < 2; ks++) {
            uint32_t af0[4], af1[4];
            {
                uint4 t0 = *(const uint4*)&Ab[((warpM * 2 + 0) * 2 + ks) * 128 + lane * 4];
                af0[0] = t0.x; af0[1] = t0.y; af0[2] = t0.z; af0[3] = t0.w;
                uint4 t1 = *(const uint4*)&Ab[((warpM * 2 + 1) * 2 + ks) * 128 + lane * 4];
                af1[0] = t1.x; af1[1] = t1.y; af1[2] = t1.z; af1[3] = t1.w;
            }
            int kgl = kgl0 + ks;
#pragma unroll
            for (int nt = 0; nt < 8; nt++) {
                int ntg = warpN * 8 + nt;
                uint2 b = *(const uint2*)&Bp[((size_t)kgl * 16 + ntg) * 64 + lane * 2];
                uint32_t bb[2] = {b.x, b.y};
                mma8(acc[0][nt], af0, bb);
                mma8(acc[1][nt], af1, bb);
            }
        }
        // store prefetched chunk c+1
        if (haveNext) {
            uint32_t* bn = Ad + ((c + 1) & 1) * 2048 + sbase;
            bn[(lane4 + 0) * 4 + slot] = f2tf(v0.x);
            bn[(lane4 + 1) * 4 + slot] = f2tf(v0.y);
            bn[(lane4 + 2) * 4 + slot] = f2tf(v0.z);
            bn[(lane4 + 3) * 4 + slot] = f2tf(v0.w);
            bn[(lane4 + 0) * 4 + slot + 2] = f2tf(v1.x);
            bn[(lane4 + 1) * 4 + slot + 2] = f2tf(v1.y);
            bn[(lane4 + 2) * 4 + slot + 2] = f2tf(v1.z);
            bn[(lane4 + 3) * 4 + slot + 2] = f2tf(v1.w);
        }
        __syncthreads();
        // panel boundary: restage B
        if (haveNext && ((c + 1) % CPP == 0)) {
            const uint4* src = (const uint4*)(pB + ((size_t)nb * KTOT + ((c + 1) / CPP) * BKP) * 128);
            uint4* dst = (uint4*)Bp;
#pragma unroll
            for (int i = 0; i < BKP / 8; i++) dst[i * 256 + tid] = src[i * 256 + tid];
            __syncthreads();
        }
    }

    // epilogue (verified R5 mapping)
#pragma unroll
    for (int mt = 0; mt < 2; mt++) {
        int rr0 = rowBase + warpM * 32 + mt * 16 + (lane >> 2);
        int rr1 = rr0 + 8;
#pragma unroll
        for (int nt = 0; nt < 8; nt++) {
            int cb = nb * 128 + warpN * 64 + nt * 8 + (lane & 3) * 2;
            float o0 = acc[mt][nt][0], o1 = acc[mt][nt][1];
            float o2 = acc[mt][nt][2], o3 = acc[mt][nt][3];
            if (BIAS) {
                float b0 = bias[cb], b1 = bias[cb + 1];
                o0 += b0; o1 += b1; o2 += b0; o3 += b1;
            }
            if (RELU) {
                o0 = fmaxf(o0, 0.f); o1 = fmaxf(o1, 0.f);
                o2 = fmaxf(o2, 0.f); o3 = fmaxf(o3, 0.f);
            }
            if (rr0 < M) { float2 s = {o0, o1}; *(float2*)(C + (size_t)rr0 * N + cb) = s; }
            if (rr1 < M) { float2 s = {o2, o3}; *(float2*)(C + (size_t)rr1 * N + cb) = s; }
        }
    }
}

// ------------------------- index dtype detection + conversion -------------------------
__global__ void k_detect(const unsigned int* __restrict__ wdata, int n_elems) {
    __shared__ int bad;
    if (threadIdx.x == 0) bad = 0;
    __syncthreads();
    int limit = n_elems < 4096 ? n_elems : 4096;
    for (int i = threadIdx.x; i < limit; i += blockDim.x)
        if (wdata[2 * i + 1] != 0u) bad = 1;
    __syncthreads();
    if (threadIdx.x == 0) g_is64 = bad ? 0 : 1;
}

__device__ __forceinline__ int clampN(int v) {
    return v < 0 ? 0 : (v >= NNODE ? NNODE - 1 : v);
}

__global__ void k_cvt_edges(const void* __restrict__ ei) {
    int e = blockIdx.x * blockDim.x + threadIdx.x;
    if (e < NE) {
        int s, d;
        if (g_is64) {
            const long long* p = (const long long*)ei;
            s = (int)p[e]; d = (int)p[NE + e];
        } else {
            const int* p = (const int*)ei;
            s = p[e]; d = p[NE + e];
        }
        g_src[e] = clampN(s);
        g_dst[e] = clampN(d);
    }
}

__global__ void k_cvt_ti(const void* __restrict__ ti) {
    int b = blockIdx.x * blockDim.x + threadIdx.x;
    if (b < BB) {
        int v;
        if (g_is64) v = (int)((const long long*)ti)[b];
        else        v = ((const int*)ti)[b];
        g_ti[b] = clampN(v);
    }
}

// ------------------------- graph preprocessing -------------------------
__global__ void k_init_deg() {
    int i = blockIdx.x * blockDim.x + threadIdx.x;
    if (i < NNODE) { g_deg[i] = 1; g_fill[i] = 0; }
    if (i == 0) { g_nt = 0; g_ns = 0; }
}

__global__ void k_deg_edges() {
    int e = blockIdx.x * blockDim.x + threadIdx.x;
    if (e < NE) atomicAdd(&g_deg[g_dst[e]], 1);
}

__global__ void k_dinv() {
    int i = blockIdx.x * blockDim.x + threadIdx.x;
    if (i < NNODE) g_dinv[i] = rsqrtf((float)g_deg[i]);
}

__global__ void k_scan() {
    const int CH = 40;
    int t = threadIdx.x;
    int lane = t & 31, wid = t >> 5;
    int beg = t * CH;
    int sum = 0;
    for (int i = 0; i < CH; i++) {
        int idx = beg + i;
        if (idx < NNODE) sum += g_deg[idx];
    }
    int v = sum;
    for (int o = 1; o < 32; o <<= 1) {
        int u = __shfl_up_sync(0xffffffffu, v, o);
        if (lane >= o) v += u;
    }
    __shared__ int wsum[32];
    if (lane == 31) wsum[wid] = v;
    __syncthreads();
    if (wid == 0) {
        int w2 = wsum[lane];
        for (int o = 1; o < 32; o <<= 1) {
            int u = __shfl_up_sync(0xffffffffu, w2, o);
            if (lane >= o) w2 += u;
        }
        wsum[lane] = w2;
    }
    __syncthreads();
    int run = v - sum + (wid > 0 ? wsum[wid - 1] : 0);
    for (int i = 0; i < CH; i++) {
        int idx = beg + i;
        if (idx < NNODE) {
            g_rowptr[idx] = run;
            run += g_deg[idx];
        }
    }
    if (t == 1023) g_rowptr[NNODE] = run;
}

__global__ void k_selfloop() {
    int n = blockIdx.x * blockDim.x + threadIdx.x;
    if (n < NNODE) {
        int pos = g_rowptr[n];
        g_col[pos] = n;
        float d = g_dinv[n];
        g_val[pos] = d * d;
        g_fill[n] = 1;
    }
}

__global__ void k_fill_edges() {
    int e = blockIdx.x * blockDim.x + threadIdx.x;
    if (e < NE) {
        int s = g_src[e];
        int d = g_dst[e];
        int pos = g_rowptr[d] + atomicAdd(&g_fill[d], 1);
        g_col[pos] = s;
        g_val[pos] = g_dinv[s] * g_dinv[d];
    }
}

// ------------------------- target-neighborhood compaction -------------------------
__global__ void k_clear_masks() {
    int i = blockIdx.x * blockDim.x + threadIdx.x;
    if (i < NNODE) { g_tmask[i] = 0; g_smask[i] = 0; }
}
__global__ void k_mark_t() {
    int b = blockIdx.x * blockDim.x + threadIdx.x;
    if (b < BB) g_tmask[g_ti[b]] = 1;
}
__global__ void k_mark_s() {
    int e = blockIdx.x * blockDim.x + threadIdx.x;
    if (e < NE && g_tmask[g_dst[e]]) g_smask[g_src[e]] = 1;
}
__global__ void k_mark_s2() {
    int n = blockIdx.x * blockDim.x + threadIdx.x;
    if (n < NNODE && g_tmask[n]) g_smask[n] = 1;
}
__global__ void k_compact() {
    int n = blockIdx.x * blockDim.x + threadIdx.x;
    if (n < NNODE) {
        if (g_tmask[n]) g_tnodes[atomicAdd(&g_nt, 1)] = n;
        if (g_smask[n]) {
            int ix = atomicAdd(&g_ns, 1);
            g_snodes[ix] = n;
            g_sidx[n] = ix;
        }
    }
}

// ------------------------- GCN aggregations (pruned, verified R7) -------------------------
__global__ void k_agg1c(const float* __restrict__ bias)
{
    int warp = (blockIdx.x * blockDim.x + threadIdx.x) >> 5;
    int lane = threadIdx.x & 31;
    if (warp >= g_ns) return;
    int node = g_snodes[warp];
    int s0 = g_rowptr[node], s1 = g_rowptr[node + 1];
    const float4* m4 = (const float4*)g_m;
    float4 acc = make_float4(0.f, 0.f, 0.f, 0.f);
    for (int e = s0; e < s1; e++) {
        float v = g_val[e];
        float4 t = m4[(size_t)g_col[e] * 32 + lane];
        acc.x = fmaf(v, t.x, acc.x); acc.y = fmaf(v, t.y, acc.y);
        acc.z = fmaf(v, t.z, acc.z); acc.w = fmaf(v, t.w, acc.w);
    }
    int c = lane * 4;
    acc.x = fmaxf(acc.x + bias[c + 0], 0.f);
    acc.y = fmaxf(acc.y + bias[c + 1], 0.f);
    acc.z = fmaxf(acc.z + bias[c + 2], 0.f);
    acc.w = fmaxf(acc.w + bias[c + 3], 0.f);
    ((float4*)g_hc)[(size_t)warp * 32 + lane] = acc;
}

__global__ void k_agg2t(const float* __restrict__ bias)
{
    int warp = (blockIdx.x * blockDim.x + threadIdx.x) >> 5;
    int lane = threadIdx.x & 31;
    if (warp >= g_nt) return;
    int node = g_tnodes[warp];
    int s0 = g_rowptr[node], s1 = g_rowptr[node + 1];
    const float4* m4 = (const float4*)g_mc;
    float4 acc = make_float4(0.f, 0.f, 0.f, 0.f);
    for (int e = s0; e < s1; e++) {
        float v = g_val[e];
        float4 t = m4[(size_t)g_sidx[g_col[e]] * 32 + lane];
        acc.x = fmaf(v, t.x, acc.x); acc.y = fmaf(v, t.y, acc.y);
        acc.z = fmaf(v, t.z, acc.z); acc.w = fmaf(v, t.w, acc.w);
    }
    int c = lane * 4;
    acc.x = fmaxf(acc.x + bias[c + 0], 0.f);
    acc.y = fmaxf(acc.y + bias[c + 1], 0.f);
    acc.z = fmaxf(acc.z + bias[c + 2], 0.f);
    acc.w = fmaxf(acc.w + bias[c + 3], 0.f);
    ((float4*)g_h2)[(size_t)node * 32 + lane] = acc;
}

// ------------------------- gather targets -------------------------
__global__ void k_gather(int t) {
    int b = blockIdx.x;
    int f = threadIdx.x;                   // 256
    int node = g_ti[b];
    float v = (f < GG) ? g_hc[(size_t)g_sidx[node] * GG + f]
                       : g_h2[(size_t)node * GG + (f - GG)];
    g_tgt[((size_t)t * BB + b) * (2 * GG) + f] = v;
}

__global__ void k_zero_h0() {
    int i = blockIdx.x * blockDim.x + threadIdx.x;
    if (i < BB * HH) g_gruh[i] = 0.f;
}

// ------------------------- GRU pointwise -------------------------
__device__ __forceinline__ float sigmoidf_(float x) { return 1.f / (1.f + expf(-x)); }

__global__ void k_gru_pt(int t) {
    int idx = blockIdx.x * blockDim.x + threadIdx.x;
    if (idx >= BB * HH) return;
    int b = idx >> 7, j = idx & 127;
    size_t gir = ((size_t)t * BB + b) * 384;
    size_t ghr = (size_t)b * 384;
    float hr = g_gh[ghr + j], hz = g_gh[ghr + 128 + j], hg = g_gh[ghr + 256 + j];
    float h = g_gruh[idx];
    float r = sigmoidf_(g_gi[gir + j] + hr);
    float z = sigmoidf_(g_gi[gir + 128 + j] + hz);
    float g = tanhf(g_gi[gir + 256 + j] + r * hg);
    float hn = (1.f - z) * g + z * h;
    g_gruh[idx] = hn;
    g_outs[(size_t)t * BB * HH + idx] = hn;
}

// ------------------------- attention + prediction head -------------------------
__global__ void k_final(const float* __restrict__ attn_w, const float* __restrict__ attn_b,
                        const float* __restrict__ pw1, const float* __restrict__ pb1,
                        const float* __restrict__ pw2, const float* __restrict__ pb2,
                        float* __restrict__ out)
{
    int b = blockIdx.x;
    int j = threadIdx.x;                   // 128
    __shared__ float so[TT][HH];
    __shared__ float red[HH];
    __shared__ float sc[TT];
    __shared__ float w8[TT];
    __shared__ float hm[16];

#pragma unroll
    for (int t = 0; t < TT; t++) so[t][j] = g_outs[((size_t)t * BB + b) * HH + j];
    float aw = attn_w[j];
    __syncthreads();

    for (int t = 0; t < TT; t++) {
        red[j] = so[t][j] * aw;
        __syncthreads();
        for (int off = 64; off > 0; off >>= 1) {
            if (j < off) red[j] += red[j + off];
            __syncthreads();
        }
        if (j == 0) sc[t] = tanhf(red[0] + attn_b[0]);
        __syncthreads();
    }
    if (j == 0) {
        float mx = sc[0];
        for (int t = 1; t < TT; t++) mx = fmaxf(mx, sc[t]);
        float s = 0.f;
        for (int t = 0; t < TT; t++) { w8[t] = expf(sc[t] - mx); s += w8[t]; }
        float inv = 1.f / s;
        for (int t = 0; t < TT; t++) w8[t] *= inv;
    }
    __syncthreads();
    float rep = 0.f;
#pragma unroll
    for (int t = 0; t < TT; t++) rep = fmaf(w8[t], so[t][j], rep);
    red[j] = rep;
    __syncthreads();
    if (j < 16) {
        float s = pb1[j];
        for (int k = 0; k < HH; k++) s = fmaf(red[k], pw1[k * 16 + j], s);
        hm[j] = fmaxf(s, 0.f);
    }
    __syncthreads();
    if (j == 0) {
        float p = pb2[0];
#pragma unroll
        for (int k = 0; k < 16; k++) p = fmaf(hm[k], pw2[k], p);
        out[b] = p;
    }
    if (j < TT) out[BB + b * TT + j] = w8[j];
}

// ------------------------- launch -------------------------
extern "C" void kernel_launch(void* const* d_in, const int* in_sizes, int n_in,
                              void* d_out, int out_size)
{
    const float* x       = (const float*)d_in[0];
    const void*  ei      = d_in[1];
    const void*  ti      = d_in[2];
    const float* proj_w  = (const float*)d_in[3];
    const float* proj_b  = (const float*)d_in[4];
    const float* gcn_w1  = (const float*)d_in[5];
    const float* gcn_b1  = (const float*)d_in[6];
    const float* gcn_w2  = (const float*)d_in[7];
    const float* gcn_b2  = (const float*)d_in[8];
    const float* gru_w_ih = (const float*)d_in[9];
    const float* gru_w_hh = (const float*)d_in[10];
    const float* gru_b_ih = (const float*)d_in[11];
    const float* gru_b_hh = (const float*)d_in[12];
    const float* attn_w  = (const float*)d_in[13];
    const float* attn_b  = (const float*)d_in[14];
    const float* pred_w1 = (const float*)d_in[15];
    const float* pred_b1 = (const float*)d_in[16];
    const float* pred_w2 = (const float*)d_in[17];
    const float* pred_b2 = (const float*)d_in[18];
    float* out = (float*)d_out;

    const int SMEM = (128 * 128 + 2 * 2048) * 4;   // 80 KB for all instantiations
    cudaFuncSetAttribute(tfgemm<256, 0, 1, 0, true,  true >, cudaFuncAttributeMaxDynamicSharedMemorySize, SMEM);
    cudaFuncSetAttribute(tfgemm<128, 1, 2, 0, false, false>, cudaFuncAttributeMaxDynamicSharedMemorySize, SMEM);
    cudaFuncSetAttribute(tfgemm<128, 2, 3, 1, false, false>, cudaFuncAttributeMaxDynamicSharedMemorySize, SMEM);
    cudaFuncSetAttribute(tfgemm<256, 3, 4, 0, false, true >, cudaFuncAttributeMaxDynamicSharedMemorySize, SMEM);
    cudaFuncSetAttribute(tfgemm<128, 4, 5, 0, false, true >, cudaFuncAttributeMaxDynamicSharedMemorySize, SMEM);

    dim3 g313(1, (NNODE + 127) / 128);
    dim3 gGi(3, (TT * BB + 127) / 128);
    dim3 gGru(3, (BB + 127) / 128);
    const int aggBlocks = (NNODE * 32 + 255) / 256;
    const int agg2Blocks = (BB * 32 + 255) / 256;

    // launch index 3 = proj GEMM (ncu captures index 3)
    k_permB<false><<<(256 * 128 + 255) / 256, 256>>>(proj_w, g_pw, 256, 128);            // 0
    k_detect<<<1, 1024>>>((const unsigned int*)ei, BB);                                  // 1
    k_cvt_ti<<<(BB + 255) / 256, 256>>>(ti);                                             // 2
    tfgemm<256, 0, 1, 0, true, true><<<g313, 256, SMEM>>>(x, g_pw, proj_b, NNODE);       // 3: proj t=0
    k_cvt_edges<<<(NE + 255) / 256, 256>>>(ei);                                          // 4
    k_permB<false><<<(128 * 128 + 255) / 256, 256>>>(gcn_w1, g_pw1, 128, 128);           // 5
    tfgemm<128, 1, 2, 0, false, false><<<g313, 256, SMEM>>>(nullptr, g_pw1, nullptr, NNODE); // 6: gemm1 t=0

    // remaining preprocessing
    k_permB<false><<<(128 * 128 + 255) / 256, 256>>>(gcn_w2, g_pw2, 128, 128);
    k_permB<true><<<(256 * 384 + 255) / 256, 256>>>(gru_w_ih, g_pwih, 256, 384);
    k_permB<true><<<(128 * 384 + 255) / 256, 256>>>(gru_w_hh, g_pwhh, 128, 384);
    k_init_deg<<<(NNODE + 255) / 256, 256>>>();
    k_deg_edges<<<(NE + 255) / 256, 256>>>();
    k_dinv<<<(NNODE + 255) / 256, 256>>>();
    k_scan<<<1, 1024>>>();
    k_selfloop<<<(NNODE + 255) / 256, 256>>>();
    k_fill_edges<<<(NE + 255) / 256, 256>>>();
    k_clear_masks<<<(NNODE + 255) / 256, 256>>>();
    k_mark_t<<<(BB + 255) / 256, 256>>>();
    k_mark_s<<<(NE + 255) / 256, 256>>>();
    k_mark_s2<<<(NNODE + 255) / 256, 256>>>();
    k_compact<<<(NNODE + 255) / 256, 256>>>();
    k_zero_h0<<<(BB * HH + 255) / 256, 256>>>();

    for (int t = 0; t < TT; t++) {
        if (t > 0) {
            const float* xt = x + (size_t)t * NNODE * FF;
            tfgemm<256, 0, 1, 0, true, true><<<g313, 256, SMEM>>>(xt, g_pw, proj_b, NNODE);
            tfgemm<128, 1, 2, 0, false, false><<<g313, 256, SMEM>>>(nullptr, g_pw1, nullptr, NNODE);
        }
        // h1 at S nodes only -> compact g_hc
        k_agg1c<<<aggBlocks, 256>>>(gcn_b1);
        // mc = hc @ gcn_w2 (Ns rows, dynamic M)
        tfgemm<128, 2, 3, 1, false, false><<<g313, 256, SMEM>>>(nullptr, g_pw2, nullptr, 0);
        // h2 at target nodes only
        k_agg2t<<<agg2Blocks, 256>>>(gcn_b2);
        // gather targets into tgt[t]
        k_gather<<<BB, 256>>>(t);
    }

    // GI = tgt (8192 x 256) @ wih^T + b_ih
    tfgemm<256, 3, 4, 0, false, true><<<gGi, 256, SMEM>>>(nullptr, g_pwih, gru_b_ih, TT * BB);

    for (int t = 0; t < TT; t++) {
        tfgemm<128, 4, 5, 0, false, true><<<gGru, 256, SMEM>>>(nullptr, g_pwhh, gru_b_hh, BB);
        k_gru_pt<<<(BB * HH + 255) / 256, 256>>>(t);
    }

    k_final<<<BB, HH>>>(attn_w, attn_b, pred_w1, pred_b1, pred_w2, pred_b2, out);
}

// round 10
// speedup vs baseline: 1.9782x; 1.9782x over previous
#include <cuda_runtime.h>
#include <cuda_bf16.h>
#include <math.h>
#include <stdint.h>

#define TT 8
#define NNODE 40000
#define FF 256
#define PP 128
#define GG 128
#define HH 128
#define BB 1024
#define NE 640000
#define NNZ (NE + NNODE)
#define MALL (TT * NNODE)      // 320000 batched rows

// ------------------------- device scratch -------------------------
__device__ __align__(16) float g_h  [(size_t)MALL * PP];     // batched proj out
__device__ __align__(16) float g_m  [(size_t)MALL * GG];     // batched gemm1 out
__device__ __align__(16) float g_hc [(size_t)MALL * GG];     // batched compact h1
__device__ __align__(16) float g_mc [(size_t)MALL * GG];     // batched gemm2 out
__device__ __align__(16) float g_h2 [(size_t)MALL * GG];     // batched h2 (target rows only)
__device__ __align__(16) float g_tgt[(size_t)TT * BB * (2 * GG)];
__device__ __align__(16) float g_gi [(size_t)TT * BB * (3 * HH)];
__device__ __align__(16) float g_gh [(size_t)BB * (3 * HH)];
__device__ __align__(16) float g_wihT[(size_t)(2 * GG) * (3 * HH)];
__device__ __align__(16) float g_whhT[(size_t)HH * (3 * HH)];
__device__ __align__(16) float g_gruh[(size_t)BB * HH];
__device__ __align__(16) float g_outs[(size_t)TT * BB * HH];
__device__ __align__(16) float g_val [NNZ];
__device__ __align__(16) float g_dinv[NNODE];
__device__ __align__(16) int   g_col [NNZ];
__device__ __align__(16) int   g_rowptr[NNODE + 1];
__device__ __align__(16) int   g_deg [NNODE];
__device__ __align__(16) int   g_fill[NNODE];
__device__ __align__(16) int   g_src [NE];
__device__ __align__(16) int   g_dst [NE];
__device__ __align__(16) int   g_ti  [BB];
__device__ __align__(16) int   g_tmask[NNODE];
__device__ __align__(16) int   g_smask[NNODE];
__device__ __align__(16) int   g_snodes[NNODE];
__device__ __align__(16) int   g_sidx [NNODE];
__device__ __align__(16) int   g_tnodes[BB];
__device__ int g_nt;
__device__ int g_ns;
__device__ int g_is64;

// ------------------------- packed f32x2 FMA -------------------------
__device__ __forceinline__ void ffma2(unsigned long long& d, unsigned long long a,
                                      unsigned long long b) {
    asm("fma.rn.f32x2 %0, %1, %2, %0;" : "+l"(d) : "l"(a), "l"(b));
}
__device__ __forceinline__ unsigned long long bcast2(float v) {
    unsigned long long o;
    uint32_t u = __float_as_uint(v);
    asm("mov.b64 %0, {%1, %1};" : "=l"(o) : "r"(u));
    return o;
}
__device__ __forceinline__ void unpk2(float& lo, float& hi, unsigned long long p) {
    uint32_t a, b;
    asm("mov.b64 {%0, %1}, %2;" : "=r"(a), "=r"(b) : "l"(p));
    lo = __uint_as_float(a);
    hi = __uint_as_float(b);
}

// ------------------------- SGEMM (128x128x16 tile, 8x8/thread, FFMA2 core) -----------
// AS: 0 ext, 1 g_h, 2 g_hc, 3 g_tgt, 4 g_gruh ; BS: 0 ext, 1 g_wihT, 2 g_whhT
// CS: 1 g_h, 2 g_m, 3 g_mc, 4 g_gi, 5 g_gh ; MSEL: 0 param M, 1 8*g_ns
template<int AS, int BS, int CS, int MSEL, bool RELU, bool BIAS>
__global__ void __launch_bounds__(256) sgemm2(const float* __restrict__ Aext,
                                              const float* __restrict__ Bext,
                                              const float* __restrict__ bias,
                                              int Mparam, int N, int K)
{
    int M = (MSEL == 1) ? 8 * g_ns : Mparam;
    int rowBase = blockIdx.y * 128;
    if (rowBase >= M) return;

    const float* A;
    if constexpr (AS == 1)      A = g_h;
    else if constexpr (AS == 2) A = g_hc;
    else if constexpr (AS == 3) A = g_tgt;
    else if constexpr (AS == 4) A = g_gruh;
    else                        A = Aext;
    const float* B;
    if constexpr (BS == 1)      B = g_wihT;
    else if constexpr (BS == 2) B = g_whhT;
    else                        B = Bext;
    float* C;
    if constexpr (CS == 1)      C = g_h;
    else if constexpr (CS == 2) C = g_m;
    else if constexpr (CS == 3) C = g_mc;
    else if constexpr (CS == 4) C = g_gi;
    else                        C = g_gh;

    const int BK = 16;
    __shared__ __align__(16) float As[BK][128];
    __shared__ __align__(16) float Bs[BK][128];
    int tid = threadIdx.x;
    int tx = tid % 16, ty = tid / 16;
    int colBase = blockIdx.x * 128;

    // acc2[i][j]: rows (ty*8+2i, ty*8+2i+1), col tx*8+j
    unsigned long long acc2[4][8];
#pragma unroll
    for (int i = 0; i < 4; i++)
#pragma unroll
        for (int j = 0; j < 8; j++) acc2[i][j] = 0ULL;

    int aRow = tid >> 2;
    int aCol = (tid & 3) * 4;
    int bRow = tid >> 5;
    int bCol = (tid & 31) * 4;

    for (int k0 = 0; k0 < K; k0 += BK) {
#pragma unroll
        for (int p = 0; p < 2; p++) {
            int r = aRow + p * 64;
            int gr = rowBase + r;
            float4 v = make_float4(0.f, 0.f, 0.f, 0.f);
            if (gr < M) v = *(const float4*)(A + (size_t)gr * K + k0 + aCol);
            As[aCol + 0][r] = v.x; As[aCol + 1][r] = v.y;
            As[aCol + 2][r] = v.z; As[aCol + 3][r] = v.w;
        }
#pragma unroll
        for (int p = 0; p < 2; p++) {
            int r = bRow + p * 8;
            float4 v = *(const float4*)(B + (size_t)(k0 + r) * N + colBase + bCol);
            *(float4*)&Bs[r][bCol] = v;
        }
        __syncthreads();
#pragma unroll
        for (int kk = 0; kk < BK; kk++) {
            unsigned long long a2[4];
#pragma unroll
            for (int i = 0; i < 4; i++)
                a2[i] = *(const unsigned long long*)&As[kk][ty * 8 + 2 * i];
#pragma unroll
            for (int j = 0; j < 8; j++) {
                unsigned long long b2 = bcast2(Bs[kk][tx * 8 + j]);
#pragma unroll
                for (int i = 0; i < 4; i++) ffma2(acc2[i][j], a2[i], b2);
            }
        }
        __syncthreads();
    }

    // epilogue: unpack row pairs
#pragma unroll
    for (int i = 0; i < 4; i++) {
        int r0 = rowBase + ty * 8 + 2 * i;
        float lo[8], hi[8];
#pragma unroll
        for (int j = 0; j < 8; j++) unpk2(lo[j], hi[j], acc2[i][j]);
#pragma unroll
        for (int h = 0; h < 2; h++) {
            int gr = r0 + h;
            if (gr >= M) continue;
            const float* rowv = h ? hi : lo;
#pragma unroll
            for (int j = 0; j < 8; j += 4) {
                int gc = colBase + tx * 8 + j;
                float4 o;
                o.x = rowv[j]; o.y = rowv[j + 1]; o.z = rowv[j + 2]; o.w = rowv[j + 3];
                if (BIAS) {
                    o.x += bias[gc]; o.y += bias[gc + 1];
                    o.z += bias[gc + 2]; o.w += bias[gc + 3];
                }
                if (RELU) {
                    o.x = fmaxf(o.x, 0.f); o.y = fmaxf(o.y, 0.f);
                    o.z = fmaxf(o.z, 0.f); o.w = fmaxf(o.w, 0.f);
                }
                *(float4*)(C + (size_t)gr * N + gc) = o;
            }
        }
    }
}

// ------------------------- index dtype detection + conversion -------------------------
__global__ void k_detect(const unsigned int* __restrict__ wdata, int n_elems) {
    __shared__ int bad;
    if (threadIdx.x == 0) bad = 0;
    __syncthreads();
    int limit = n_elems < 4096 ? n_elems : 4096;
    for (int i = threadIdx.x; i < limit; i += blockDim.x)
        if (wdata[2 * i + 1] != 0u) bad = 1;
    __syncthreads();
    if (threadIdx.x == 0) g_is64 = bad ? 0 : 1;
}

__device__ __forceinline__ int clampN(int v) {
    return v < 0 ? 0 : (v >= NNODE ? NNODE - 1 : v);
}

__global__ void k_cvt_edges(const void* __restrict__ ei) {
    int e = blockIdx.x * blockDim.x + threadIdx.x;
    if (e < NE) {
        int s, d;
        if (g_is64) {
            const long long* p = (const long long*)ei;
            s = (int)p[e]; d = (int)p[NE + e];
        } else {
            const int* p = (const int*)ei;
            s = p[e]; d = p[NE + e];
        }
        g_src[e] = clampN(s);
        g_dst[e] = clampN(d);
    }
}

__global__ void k_cvt_ti(const void* __restrict__ ti) {
    int b = blockIdx.x * blockDim.x + threadIdx.x;
    if (b < BB) {
        int v;
        if (g_is64) v = (int)((const long long*)ti)[b];
        else        v = ((const int*)ti)[b];
        g_ti[b] = clampN(v);
    }
}

// ------------------------- graph preprocessing -------------------------
__global__ void k_init_deg() {
    int i = blockIdx.x * blockDim.x + threadIdx.x;
    if (i < NNODE) { g_deg[i] = 1; g_fill[i] = 0; }
    if (i == 0) { g_nt = 0; g_ns = 0; }
}

__global__ void k_deg_edges() {
    int e = blockIdx.x * blockDim.x + threadIdx.x;
    if (e < NE) atomicAdd(&g_deg[g_dst[e]], 1);
}

__global__ void k_dinv() {
    int i = blockIdx.x * blockDim.x + threadIdx.x;
    if (i < NNODE) g_dinv[i] = rsqrtf((float)g_deg[i]);
}

__global__ void k_scan() {
    const int CH = 40;
    int t = threadIdx.x;
    int lane = t & 31, wid = t >> 5;
    int beg = t * CH;
    int sum = 0;
    for (int i = 0; i < CH; i++) {
        int idx = beg + i;
        if (idx < NNODE) sum += g_deg[idx];
    }
    int v = sum;
    for (int o = 1; o < 32; o <<= 1) {
        int u = __shfl_up_sync(0xffffffffu, v, o);
        if (lane >= o) v += u;
    }
    __shared__ int wsum[32];
    if (lane == 31) wsum[wid] = v;
    __syncthreads();
    if (wid == 0) {
        int w2 = wsum[lane];
        for (int o = 1; o < 32; o <<= 1) {
            int u = __shfl_up_sync(0xffffffffu, w2, o);
            if (lane >= o) w2 += u;
        }
        wsum[lane] = w2;
    }
    __syncthreads();
    int run = v - sum + (wid > 0 ? wsum[wid - 1] : 0);
    for (int i = 0; i < CH; i++) {
        int idx = beg + i;
        if (idx < NNODE) {
            g_rowptr[idx] = run;
            run += g_deg[idx];
        }
    }
    if (t == 1023) g_rowptr[NNODE] = run;
}

__global__ void k_selfloop() {
    int n = blockIdx.x * blockDim.x + threadIdx.x;
    if (n < NNODE) {
        int pos = g_rowptr[n];
        g_col[pos] = n;
        float d = g_dinv[n];
        g_val[pos] = d * d;
        g_fill[n] = 1;
    }
}

__global__ void k_fill_edges() {
    int e = blockIdx.x * blockDim.x + threadIdx.x;
    if (e < NE) {
        int s = g_src[e];
        int d = g_dst[e];
        int pos = g_rowptr[d] + atomicAdd(&g_fill[d], 1);
        g_col[pos] = s;
        g_val[pos] = g_dinv[s] * g_dinv[d];
    }
}

// ------------------------- target-neighborhood compaction -------------------------
__global__ void k_clear_masks() {
    int i = blockIdx.x * blockDim.x + threadIdx.x;
    if (i < NNODE) { g_tmask[i] = 0; g_smask[i] = 0; }
}
__global__ void k_mark_t() {
    int b = blockIdx.x * blockDim.x + threadIdx.x;
    if (b < BB) g_tmask[g_ti[b]] = 1;
}
__global__ void k_mark_s() {
    int e = blockIdx.x * blockDim.x + threadIdx.x;
    if (e < NE && g_tmask[g_dst[e]]) g_smask[g_src[e]] = 1;
}
__global__ void k_mark_s2() {
    int n = blockIdx.x * blockDim.x + threadIdx.x;
    if (n < NNODE && g_tmask[n]) g_smask[n] = 1;
}
__global__ void k_compact() {
    int n = blockIdx.x * blockDim.x + threadIdx.x;
    if (n < NNODE) {
        if (g_tmask[n]) g_tnodes[atomicAdd(&g_nt, 1)] = n;
        if (g_smask[n]) {
            int ix = atomicAdd(&g_ns, 1);
            g_snodes[ix] = n;
            g_sidx[n] = ix;
        }
    }
}

// ------------------------- batched GCN aggregations -------------------------
// layer-1 at S nodes for all t: warp = t*g_ns + i ; m row = t*NNODE + col ; out row = warp
__global__ void k_agg1c_all(const float* __restrict__ bias)
{
    int warp = (blockIdx.x * blockDim.x + threadIdx.x) >> 5;
    int lane = threadIdx.x & 31;
    int ns = g_ns;
    if (warp >= TT * ns) return;
    int t = warp / ns;
    int i = warp - t * ns;
    int node = g_snodes[i];
    int s0 = g_rowptr[node], s1 = g_rowptr[node + 1];
    const float4* m4 = (const float4*)g_m;
    size_t mbase = (size_t)t * NNODE * 32;
    float4 acc = make_float4(0.f, 0.f, 0.f, 0.f);
    for (int e = s0; e < s1; e++) {
        float v = g_val[e];
        float4 x = m4[mbase + (size_t)g_col[e] * 32 + lane];
        acc.x = fmaf(v, x.x, acc.x); acc.y = fmaf(v, x.y, acc.y);
        acc.z = fmaf(v, x.z, acc.z); acc.w = fmaf(v, x.w, acc.w);
    }
    int c = lane * 4;
    acc.x = fmaxf(acc.x + bias[c + 0], 0.f);
    acc.y = fmaxf(acc.y + bias[c + 1], 0.f);
    acc.z = fmaxf(acc.z + bias[c + 2], 0.f);
    acc.w = fmaxf(acc.w + bias[c + 3], 0.f);
    ((float4*)g_hc)[(size_t)warp * 32 + lane] = acc;
}

// layer-2 at target nodes for all t: warp = t*g_nt + i ; mc row = t*g_ns + sidx ;
// out h2 row = t*NNODE + node
__global__ void k_agg2t_all(const float* __restrict__ bias)
{
    int warp = (blockIdx.x * blockDim.x + threadIdx.x) >> 5;
    int lane = threadIdx.x & 31;
    int nt = g_nt;
    if (warp >= TT * nt) return;
    int t = warp / nt;
    int i = warp - t * nt;
    int node = g_tnodes[i];
    int s0 = g_rowptr[node], s1 = g_rowptr[node + 1];
    const float4* m4 = (const float4*)g_mc;
    size_t mbase = (size_t)t * g_ns * 32;
    float4 acc = make_float4(0.f, 0.f, 0.f, 0.f);
    for (int e = s0; e < s1; e++) {
        float v = g_val[e];
        float4 x = m4[mbase + (size_t)g_sidx[g_col[e]] * 32 + lane];
        acc.x = fmaf(v, x.x, acc.x); acc.y = fmaf(v, x.y, acc.y);
        acc.z = fmaf(v, x.z, acc.z); acc.w = fmaf(v, x.w, acc.w);
    }
    int c = lane * 4;
    acc.x = fmaxf(acc.x + bias[c + 0], 0.f);
    acc.y = fmaxf(acc.y + bias[c + 1], 0.f);
    acc.z = fmaxf(acc.z + bias[c + 2], 0.f);
    acc.w = fmaxf(acc.w + bias[c + 3], 0.f);
    ((float4*)g_h2)[((size_t)t * NNODE + node) * 32 + lane] = acc;
}

// ------------------------- gather targets (all t) -------------------------
__global__ void k_gather_all() {
    int b = blockIdx.x;
    int t = blockIdx.y;
    int f = threadIdx.x;                   // 256
    int node = g_ti[b];
    float v = (f < GG) ? g_hc[((size_t)t * g_ns + g_sidx[node]) * GG + f]
                       : g_h2[((size_t)t * NNODE + node) * GG + (f - GG)];
    g_tgt[((size_t)t * BB + b) * (2 * GG) + f] = v;
}

// ------------------------- weight transposes / zero -------------------------
__global__ void k_transpose_wih(const float* __restrict__ w) {
    int i = blockIdx.x * blockDim.x + threadIdx.x;
    if (i < 384 * 256) {
        int jj = i / 256, k = i % 256;
        g_wihT[(size_t)k * 384 + jj] = w[i];
    }
}
__global__ void k_transpose_whh(const float* __restrict__ w) {
    int i = blockIdx.x * blockDim.x + threadIdx.x;
    if (i < 384 * 128) {
        int jj = i / 128, k = i % 128;
        g_whhT[(size_t)k * 384 + jj] = w[i];
    }
}
__global__ void k_zero_h0() {
    int i = blockIdx.x * blockDim.x + threadIdx.x;
    if (i < BB * HH) g_gruh[i] = 0.f;
}

// ------------------------- GRU pointwise -------------------------
__device__ __forceinline__ float sigmoidf_(float x) { return 1.f / (1.f + expf(-x)); }

__global__ void k_gru_pt(int t) {
    int idx = blockIdx.x * blockDim.x + threadIdx.x;
    if (idx >= BB * HH) return;
    int b = idx >> 7, j = idx & 127;
    size_t gir = ((size_t)t * BB + b) * 384;
    size_t ghr = (size_t)b * 384;
    float hr = g_gh[ghr + j], hz = g_gh[ghr + 128 + j], hg = g_gh[ghr + 256 + j];
    float h = g_gruh[idx];
    float r = sigmoidf_(g_gi[gir + j] + hr);
    float z = sigmoidf_(g_gi[gir + 128 + j] + hz);
    float g = tanhf(g_gi[gir + 256 + j] + r * hg);
    float hn = (1.f - z) * g + z * h;
    g_gruh[idx] = hn;
    g_outs[(size_t)t * BB * HH + idx] = hn;
}

// ------------------------- attention + prediction head -------------------------
__global__ void k_final(const float* __restrict__ attn_w, const float* __restrict__ attn_b,
                        const float* __restrict__ pw1, const float* __restrict__ pb1,
                        const float* __restrict__ pw2, const float* __restrict__ pb2,
                        float* __restrict__ out)
{
    int b = blockIdx.x;
    int j = threadIdx.x;                   // 128
    __shared__ float so[TT][HH];
    __shared__ float red[HH];
    __shared__ float sc[TT];
    __shared__ float w8[TT];
    __shared__ float hm[16];

#pragma unroll
    for (int t = 0; t < TT; t++) so[t][j] = g_outs[((size_t)t * BB + b) * HH + j];
    float aw = attn_w[j];
    __syncthreads();

    for (int t = 0; t < TT; t++) {
        red[j] = so[t][j] * aw;
        __syncthreads();
        for (int off = 64; off > 0; off >>= 1) {
            if (j < off) red[j] += red[j + off];
            __syncthreads();
        }
        if (j == 0) sc[t] = tanhf(red[0] + attn_b[0]);
        __syncthreads();
    }
    if (j == 0) {
        float mx = sc[0];
        for (int t = 1; t < TT; t++) mx = fmaxf(mx, sc[t]);
        float s = 0.f;
        for (int t = 0; t < TT; t++) { w8[t] = expf(sc[t] - mx); s += w8[t]; }
        float inv = 1.f / s;
        for (int t = 0; t < TT; t++) w8[t] *= inv;
    }
    __syncthreads();
    float rep = 0.f;
#pragma unroll
    for (int t = 0; t < TT; t++) rep = fmaf(w8[t], so[t][j], rep);
    red[j] = rep;
    __syncthreads();
    if (j < 16) {
        float s = pb1[j];
        for (int k = 0; k < HH; k++) s = fmaf(red[k], pw1[k * 16 + j], s);
        hm[j] = fmaxf(s, 0.f);
    }
    __syncthreads();
    if (j == 0) {
        float p = pb2[0];
#pragma unroll
        for (int k = 0; k < 16; k++) p = fmaf(hm[k], pw2[k], p);
        out[b] = p;
    }
    if (j < TT) out[BB + b * TT + j] = w8[j];
}

// ------------------------- launch -------------------------
extern "C" void kernel_launch(void* const* d_in, const int* in_sizes, int n_in,
                              void* d_out, int out_size)
{
    const float* x       = (const float*)d_in[0];
    const void*  ei      = d_in[1];
    const void*  ti      = d_in[2];
    const float* proj_w  = (const float*)d_in[3];
    const float* proj_b  = (const float*)d_in[4];
    const float* gcn_w1  = (const float*)d_in[5];
    const float* gcn_b1  = (const float*)d_in[6];
    const float* gcn_w2  = (const float*)d_in[7];
    const float* gcn_b2  = (const float*)d_in[8];
    const float* gru_w_ih = (const float*)d_in[9];
    const float* gru_w_hh = (const float*)d_in[10];
    const float* gru_b_ih = (const float*)d_in[11];
    const float* gru_b_hh = (const float*)d_in[12];
    const float* attn_w  = (const float*)d_in[13];
    const float* attn_b  = (const float*)d_in[14];
    const float* pred_w1 = (const float*)d_in[15];
    const float* pred_b1 = (const float*)d_in[16];
    const float* pred_w2 = (const float*)d_in[17];
    const float* pred_b2 = (const float*)d_in[18];
    float* out = (float*)d_out;

    dim3 gAll(1, (MALL + 127) / 128);            // 2500 blocks, batched GEMMs
    dim3 gGi(3, (TT * BB + 127) / 128);
    dim3 gGru(3, (BB + 127) / 128);
    const int agg1Blocks = (MALL * 32 + 255) / 256;        // 8*40000 warps worst case
    const int agg2Blocks = (TT * BB * 32 + 255) / 256;     // 8*1024 warps worst case
    dim3 gGather(BB, TT);

    // index 3 = batched proj GEMM (ncu captures launch 3)
    k_detect<<<1, 1024>>>((const unsigned int*)ei, BB);                          // 0
    k_cvt_ti<<<(BB + 255) / 256, 256>>>(ti);                                     // 1
    k_cvt_edges<<<(NE + 255) / 256, 256>>>(ei);                                  // 2
    sgemm2<0, 0, 1, 0, true, true><<<gAll, 256>>>(x, proj_w, proj_b, MALL, PP, FF);   // 3: proj ALL t
    k_transpose_wih<<<(384 * 256 + 255) / 256, 256>>>(gru_w_ih);                 // 4
    sgemm2<1, 0, 2, 0, false, false><<<gAll, 256>>>(nullptr, gcn_w1, nullptr, MALL, GG, PP); // 5: gemm1 ALL t
    k_transpose_whh<<<(384 * 128 + 255) / 256, 256>>>(gru_w_hh);                 // 6

    // graph preprocessing
    k_init_deg<<<(NNODE + 255) / 256, 256>>>();
    k_deg_edges<<<(NE + 255) / 256, 256>>>();
    k_dinv<<<(NNODE + 255) / 256, 256>>>();
    k_scan<<<1, 1024>>>();
    k_selfloop<<<(NNODE + 255) / 256, 256>>>();
    k_fill_edges<<<(NE + 255) / 256, 256>>>();
    k_clear_masks<<<(NNODE + 255) / 256, 256>>>();
    k_mark_t<<<(BB + 255) / 256, 256>>>();
    k_mark_s<<<(NE + 255) / 256, 256>>>();
    k_mark_s2<<<(NNODE + 255) / 256, 256>>>();
    k_compact<<<(NNODE + 255) / 256, 256>>>();
    k_zero_h0<<<(BB * HH + 255) / 256, 256>>>();

    // batched GCN pipeline (all t at once)
    k_agg1c_all<<<agg1Blocks, 256>>>(gcn_b1);
    sgemm2<2, 0, 3, 1, false, false><<<gAll, 256>>>(nullptr, gcn_w2, nullptr, 0, GG, GG);
    k_agg2t_all<<<agg2Blocks, 256>>>(gcn_b2);
    k_gather_all<<<gGather, 256>>>();

    // GI = tgt (8192 x 256) @ wihT + b_ih
    sgemm2<3, 1, 4, 0, false, true><<<gGi, 256>>>(nullptr, nullptr, gru_b_ih, TT * BB, 3 * HH, 2 * GG);

    for (int t = 0; t < TT; t++) {
        sgemm2<4, 2, 5, 0, false, true><<<gGru, 256>>>(nullptr, nullptr, gru_b_hh, BB, 3 * HH, HH);
        k_gru_pt<<<(BB * HH + 255) / 256, 256>>>(t);
    }

    k_final<<<BB, HH>>>(attn_w, attn_b, pred_w1, pred_b1, pred_w2, pred_b2, out);
}

// round 11
// speedup vs baseline: 2.4424x; 1.2347x over previous
#include <cuda_runtime.h>
#include <cuda_bf16.h>
#include <math.h>
#include <stdint.h>

#define TT 8
#define NNODE 40000
#define FF 256
#define PP 128
#define GG 128
#define HH 128
#define BB 1024
#define NE 640000
#define NNZ (NE + NNODE)
#define MALL (TT * NNODE)      // 320000 batched rows

// ------------------------- device scratch -------------------------
__device__ __align__(16) float g_h  [(size_t)MALL * PP];       // batched proj out
__device__ __align__(16) float g_m  [(size_t)MALL * GG];       // agg1(h) at S nodes (8*ns rows)
__device__ __align__(16) float g_hc [(size_t)MALL * GG];       // h1c = relu(agg1@W1+b1) (8*ns rows)
__device__ __align__(16) float g_mc [(size_t)TT * BB * GG];    // agg2(h1c) at targets (8*nt rows)
__device__ __align__(16) float g_h2 [(size_t)TT * BB * GG];    // h2c (8*nt rows)
__device__ __align__(16) float g_tgt[(size_t)TT * BB * (2 * GG)];
__device__ __align__(16) float g_gi [(size_t)TT * BB * (3 * HH)];
__device__ __align__(16) float g_gh [(size_t)BB * (3 * HH)];
__device__ __align__(16) float g_wihT[(size_t)(2 * GG) * (3 * HH)];
__device__ __align__(16) float g_whhT[(size_t)HH * (3 * HH)];
__device__ __align__(16) float g_gruh[(size_t)BB * HH];
__device__ __align__(16) float g_outs[(size_t)TT * BB * HH];
__device__ __align__(16) float g_val [NNZ];
__device__ __align__(16) float g_dinv[NNODE];
__device__ __align__(16) int   g_col [NNZ];
__device__ __align__(16) int   g_rowptr[NNODE + 1];
__device__ __align__(16) int   g_deg [NNODE];
__device__ __align__(16) int   g_fill[NNODE];
__device__ __align__(16) int   g_src [NE];
__device__ __align__(16) int   g_dst [NE];
__device__ __align__(16) int   g_ti  [BB];
__device__ __align__(16) int   g_tmask[NNODE];
__device__ __align__(16) int   g_smask[NNODE];
__device__ __align__(16) int   g_snodes[NNODE];
__device__ __align__(16) int   g_sidx [NNODE];
__device__ __align__(16) int   g_tidx [NNODE];
__device__ __align__(16) int   g_tnodes[BB];
__device__ int g_nt;
__device__ int g_ns;
__device__ int g_is64;

// ------------------------- packed f32x2 FMA -------------------------
__device__ __forceinline__ void ffma2(unsigned long long& d, unsigned long long a,
                                      unsigned long long b) {
    asm("fma.rn.f32x2 %0, %1, %2, %0;" : "+l"(d) : "l"(a), "l"(b));
}
__device__ __forceinline__ unsigned long long bcast2(float v) {
    unsigned long long o;
    uint32_t u = __float_as_uint(v);
    asm("mov.b64 %0, {%1, %1};" : "=l"(o) : "r"(u));
    return o;
}
__device__ __forceinline__ void unpk2(float& lo, float& hi, unsigned long long p) {
    uint32_t a, b;
    asm("mov.b64 {%0, %1}, %2;" : "=r"(a), "=r"(b) : "l"(p));
    lo = __uint_as_float(a);
    hi = __uint_as_float(b);
}

// ------------------------- SGEMM (128x128x16 tile, 8x8/thread, FFMA2 col-pairs) ------
// AS: 0 ext, 1 g_m, 2 g_mc, 3 g_tgt, 4 g_gruh ; BS: 0 ext, 1 g_wihT, 2 g_whhT
// CS: 1 g_h, 2 g_hc, 3 g_h2, 4 g_gi, 5 g_gh ; MSEL: 0 param, 1 8*g_ns, 2 8*g_nt
template<int AS, int BS, int CS, int MSEL, bool RELU, bool BIAS>
__global__ void __launch_bounds__(256) sgemm2(const float* __restrict__ Aext,
                                              const float* __restrict__ Bext,
                                              const float* __restrict__ bias,
                                              int Mparam, int N, int K)
{
    int M;
    if constexpr (MSEL == 1)      M = 8 * g_ns;
    else if constexpr (MSEL == 2) M = 8 * g_nt;
    else                          M = Mparam;
    int rowBase = blockIdx.y * 128;
    if (rowBase >= M) return;

    const float* A;
    if constexpr (AS == 1)      A = g_m;
    else if constexpr (AS == 2) A = g_mc;
    else if constexpr (AS == 3) A = g_tgt;
    else if constexpr (AS == 4) A = g_gruh;
    else                        A = Aext;
    const float* B;
    if constexpr (BS == 1)      B = g_wihT;
    else if constexpr (BS == 2) B = g_whhT;
    else                        B = Bext;
    float* C;
    if constexpr (CS == 1)      C = g_h;
    else if constexpr (CS == 2) C = g_hc;
    else if constexpr (CS == 3) C = g_h2;
    else if constexpr (CS == 4) C = g_gi;
    else                        C = g_gh;

    const int BK = 16;
    __shared__ __align__(16) float As[BK][128];
    __shared__ __align__(16) float Bs[BK][128];
    int tid = threadIdx.x;
    int tx = tid % 16, ty = tid / 16;
    int colBase = blockIdx.x * 128;

    // acc2[i][j]: row ty*8+i, cols (tx*8+2j, tx*8+2j+1)
    unsigned long long acc2[8][4];
#pragma unroll
    for (int i = 0; i < 8; i++)
#pragma unroll
        for (int j = 0; j < 4; j++) acc2[i][j] = 0ULL;

    int aRow = tid >> 2;
    int aCol = (tid & 3) * 4;
    int bRow = tid >> 5;
    int bCol = (tid & 31) * 4;

    for (int k0 = 0; k0 < K; k0 += BK) {
#pragma unroll
        for (int p = 0; p < 2; p++) {
            int r = aRow + p * 64;
            int gr = rowBase + r;
            float4 v = make_float4(0.f, 0.f, 0.f, 0.f);
            if (gr < M) v = *(const float4*)(A + (size_t)gr * K + k0 + aCol);
            As[aCol + 0][r] = v.x; As[aCol + 1][r] = v.y;
            As[aCol + 2][r] = v.z; As[aCol + 3][r] = v.w;
        }
#pragma unroll
        for (int p = 0; p < 2; p++) {
            int r = bRow + p * 8;
            float4 v = *(const float4*)(B + (size_t)(k0 + r) * N + colBase + bCol);
            *(float4*)&Bs[r][bCol] = v;
        }
        __syncthreads();
#pragma unroll
        for (int kk = 0; kk < BK; kk++) {
            // A: 8 row-values (broadcast within half-warp), packed {v,v}
            float4 a0 = *(const float4*)&As[kk][ty * 8];
            float4 a1 = *(const float4*)&As[kk][ty * 8 + 4];
            unsigned long long av[8];
            av[0] = bcast2(a0.x); av[1] = bcast2(a0.y);
            av[2] = bcast2(a0.z); av[3] = bcast2(a0.w);
            av[4] = bcast2(a1.x); av[5] = bcast2(a1.y);
            av[6] = bcast2(a1.z); av[7] = bcast2(a1.w);
            // B: 4 natural col-pairs via 2x LDS.128
            ulonglong2 b0 = *(const ulonglong2*)&Bs[kk][tx * 8];
            ulonglong2 b1 = *(const ulonglong2*)&Bs[kk][tx * 8 + 4];
            unsigned long long bv[4] = {b0.x, b0.y, b1.x, b1.y};
#pragma unroll
            for (int i = 0; i < 8; i++)
#pragma unroll
                for (int j = 0; j < 4; j++) ffma2(acc2[i][j], av[i], bv[j]);
        }
        __syncthreads();
    }

    // epilogue
#pragma unroll
    for (int i = 0; i < 8; i++) {
        int gr = rowBase + ty * 8 + i;
        if (gr >= M) continue;
        float c[8];
#pragma unroll
        for (int j = 0; j < 4; j++) unpk2(c[2 * j], c[2 * j + 1], acc2[i][j]);
#pragma unroll
        for (int j = 0; j < 8; j += 4) {
            int gc = colBase + tx * 8 + j;
            float4 o;
            o.x = c[j]; o.y = c[j + 1]; o.z = c[j + 2]; o.w = c[j + 3];
            if (BIAS) {
                o.x += bias[gc]; o.y += bias[gc + 1];
                o.z += bias[gc + 2]; o.w += bias[gc + 3];
            }
            if (RELU) {
                o.x = fmaxf(o.x, 0.f); o.y = fmaxf(o.y, 0.f);
                o.z = fmaxf(o.z, 0.f); o.w = fmaxf(o.w, 0.f);
            }
            *(float4*)(C + (size_t)gr * N + gc) = o;
        }
    }
}

// ------------------------- index dtype detection + conversion -------------------------
__global__ void k_detect(const unsigned int* __restrict__ wdata, int n_elems) {
    __shared__ int bad;
    if (threadIdx.x == 0) bad = 0;
    __syncthreads();
    int limit = n_elems < 4096 ? n_elems : 4096;
    for (int i = threadIdx.x; i < limit; i += blockDim.x)
        if (wdata[2 * i + 1] != 0u) bad = 1;
    __syncthreads();
    if (threadIdx.x == 0) g_is64 = bad ? 0 : 1;
}

__device__ __forceinline__ int clampN(int v) {
    return v < 0 ? 0 : (v >= NNODE ? NNODE - 1 : v);
}

__global__ void k_cvt_edges(const void* __restrict__ ei) {
    int e = blockIdx.x * blockDim.x + threadIdx.x;
    if (e < NE) {
        int s, d;
        if (g_is64) {
            const long long* p = (const long long*)ei;
            s = (int)p[e]; d = (int)p[NE + e];
        } else {
            const int* p = (const int*)ei;
            s = p[e]; d = p[NE + e];
        }
        g_src[e] = clampN(s);
        g_dst[e] = clampN(d);
    }
}

__global__ void k_cvt_ti(const void* __restrict__ ti) {
    int b = blockIdx.x * blockDim.x + threadIdx.x;
    if (b < BB) {
        int v;
        if (g_is64) v = (int)((const long long*)ti)[b];
        else        v = ((const int*)ti)[b];
        g_ti[b] = clampN(v);
    }
}

// ------------------------- graph preprocessing -------------------------
__global__ void k_init_deg() {
    int i = blockIdx.x * blockDim.x + threadIdx.x;
    if (i < NNODE) { g_deg[i] = 1; g_fill[i] = 0; }
    if (i == 0) { g_nt = 0; g_ns = 0; }
}

__global__ void k_deg_edges() {
    int e = blockIdx.x * blockDim.x + threadIdx.x;
    if (e < NE) atomicAdd(&g_deg[g_dst[e]], 1);
}

__global__ void k_dinv() {
    int i = blockIdx.x * blockDim.x + threadIdx.x;
    if (i < NNODE) g_dinv[i] = rsqrtf((float)g_deg[i]);
}

__global__ void k_scan() {
    const int CH = 40;
    int t = threadIdx.x;
    int lane = t & 31, wid = t >> 5;
    int beg = t * CH;
    int sum = 0;
    for (int i = 0; i < CH; i++) {
        int idx = beg + i;
        if (idx < NNODE) sum += g_deg[idx];
    }
    int v = sum;
    for (int o = 1; o < 32; o <<= 1) {
        int u = __shfl_up_sync(0xffffffffu, v, o);
        if (lane >= o) v += u;
    }
    __shared__ int wsum[32];
    if (lane == 31) wsum[wid] = v;
    __syncthreads();
    if (wid == 0) {
        int w2 = wsum[lane];
        for (int o = 1; o < 32; o <<= 1) {
            int u = __shfl_up_sync(0xffffffffu, w2, o);
            if (lane >= o) w2 += u;
        }
        wsum[lane] = w2;
    }
    __syncthreads();
    int run = v - sum + (wid > 0 ? wsum[wid - 1] : 0);
    for (int i = 0; i < CH; i++) {
        int idx = beg + i;
        if (idx < NNODE) {
            g_rowptr[idx] = run;
            run += g_deg[idx];
        }
    }
    if (t == 1023) g_rowptr[NNODE] = run;
}

__global__ void k_selfloop() {
    int n = blockIdx.x * blockDim.x + threadIdx.x;
    if (n < NNODE) {
        int pos = g_rowptr[n];
        g_col[pos] = n;
        float d = g_dinv[n];
        g_val[pos] = d * d;
        g_fill[n] = 1;
    }
}

__global__ void k_fill_edges() {
    int e = blockIdx.x * blockDim.x + threadIdx.x;
    if (e < NE) {
        int s = g_src[e];
        int d = g_dst[e];
        int pos = g_rowptr[d] + atomicAdd(&g_fill[d], 1);
        g_col[pos] = s;
        g_val[pos] = g_dinv[s] * g_dinv[d];
    }
}

// ------------------------- target-neighborhood compaction -------------------------
__global__ void k_clear_masks() {
    int i = blockIdx.x * blockDim.x + threadIdx.x;
    if (i < NNODE) { g_tmask[i] = 0; g_smask[i] = 0; }
}
__global__ void k_mark_t() {
    int b = blockIdx.x * blockDim.x + threadIdx.x;
    if (b < BB) g_tmask[g_ti[b]] = 1;
}
__global__ void k_mark_s() {
    int e = blockIdx.x * blockDim.x + threadIdx.x;
    if (e < NE && g_tmask[g_dst[e]]) g_smask[g_src[e]] = 1;
}
__global__ void k_mark_s2() {
    int n = blockIdx.x * blockDim.x + threadIdx.x;
    if (n < NNODE && g_tmask[n]) g_smask[n] = 1;
}
__global__ void k_compact() {
    int n = blockIdx.x * blockDim.x + threadIdx.x;
    if (n < NNODE) {
        if (g_tmask[n]) {
            int ix = atomicAdd(&g_nt, 1);
            g_tnodes[ix] = n;
            g_tidx[n] = ix;
        }
        if (g_smask[n]) {
            int ix = atomicAdd(&g_ns, 1);
            g_snodes[ix] = n;
            g_sidx[n] = ix;
        }
    }
}

// ------------------------- batched aggregations (pre-GEMM, linearity) ----------------
// agg1 at S nodes for all t: gathers h rows (full graph), raw sum, out g_m row t*ns+i
__global__ void k_agg1_all()
{
    int warp = (blockIdx.x * blockDim.x + threadIdx.x) >> 5;
    int lane = threadIdx.x & 31;
    int ns = g_ns;
    if (warp >= TT * ns) return;
    int t = warp / ns;
    int i = warp - t * ns;
    int node = g_snodes[i];
    int s0 = g_rowptr[node], s1 = g_rowptr[node + 1];
    const float4* h4 = (const float4*)g_h;
    size_t hbase = (size_t)t * NNODE * 32;
    float4 acc = make_float4(0.f, 0.f, 0.f, 0.f);
    for (int e = s0; e < s1; e++) {
        float v = g_val[e];
        float4 x = h4[hbase + (size_t)g_col[e] * 32 + lane];
        acc.x = fmaf(v, x.x, acc.x); acc.y = fmaf(v, x.y, acc.y);
        acc.z = fmaf(v, x.z, acc.z); acc.w = fmaf(v, x.w, acc.w);
    }
    ((float4*)g_m)[(size_t)warp * 32 + lane] = acc;
}

// agg2 at target nodes for all t: gathers h1c rows (compact), raw sum, out g_mc row t*nt+i
__global__ void k_agg2_all()
{
    int warp = (blockIdx.x * blockDim.x + threadIdx.x) >> 5;
    int lane = threadIdx.x & 31;
    int nt = g_nt;
    if (warp >= TT * nt) return;
    int t = warp / nt;
    int i = warp - t * nt;
    int node = g_tnodes[i];
    int s0 = g_rowptr[node], s1 = g_rowptr[node + 1];
    const float4* h4 = (const float4*)g_hc;
    size_t hbase = (size_t)t * g_ns * 32;
    float4 acc = make_float4(0.f, 0.f, 0.f, 0.f);
    for (int e = s0; e < s1; e++) {
        float v = g_val[e];
        float4 x = h4[hbase + (size_t)g_sidx[g_col[e]] * 32 + lane];
        acc.x = fmaf(v, x.x, acc.x); acc.y = fmaf(v, x.y, acc.y);
        acc.z = fmaf(v, x.z, acc.z); acc.w = fmaf(v, x.w, acc.w);
    }
    ((float4*)g_mc)[(size_t)warp * 32 + lane] = acc;
}

// ------------------------- gather targets (all t) -------------------------
__global__ void k_gather_all() {
    int b = blockIdx.x;
    int t = blockIdx.y;
    int f = threadIdx.x;                   // 256
    int node = g_ti[b];
    float v = (f < GG) ? g_hc[((size_t)t * g_ns + g_sidx[node]) * GG + f]
                       : g_h2[((size_t)t * g_nt + g_tidx[node]) * GG + (f - GG)];
    g_tgt[((size_t)t * BB + b) * (2 * GG) + f] = v;
}

// ------------------------- weight transposes / zero -------------------------
__global__ void k_transpose_wih(const float* __restrict__ w) {
    int i = blockIdx.x * blockDim.x + threadIdx.x;
    if (i < 384 * 256) {
        int jj = i / 256, k = i % 256;
        g_wihT[(size_t)k * 384 + jj] = w[i];
    }
}
__global__ void k_transpose_whh(const float* __restrict__ w) {
    int i = blockIdx.x * blockDim.x + threadIdx.x;
    if (i < 384 * 128) {
        int jj = i / 128, k = i % 128;
        g_whhT[(size_t)k * 384 + jj] = w[i];
    }
}
__global__ void k_zero_h0() {
    int i = blockIdx.x * blockDim.x + threadIdx.x;
    if (i < BB * HH) g_gruh[i] = 0.f;
}

// ------------------------- GRU pointwise -------------------------
__device__ __forceinline__ float sigmoidf_(float x) { return 1.f / (1.f + expf(-x)); }

__global__ void k_gru_pt(int t) {
    int idx = blockIdx.x * blockDim.x + threadIdx.x;
    if (idx >= BB * HH) return;
    int b = idx >> 7, j = idx & 127;
    size_t gir = ((size_t)t * BB + b) * 384;
    size_t ghr = (size_t)b * 384;
    float hr = g_gh[ghr + j], hz = g_gh[ghr + 128 + j], hg = g_gh[ghr + 256 + j];
    float h = g_gruh[idx];
    float r = sigmoidf_(g_gi[gir + j] + hr);
    float z = sigmoidf_(g_gi[gir + 128 + j] + hz);
    float g = tanhf(g_gi[gir + 256 + j] + r * hg);
    float hn = (1.f - z) * g + z * h;
    g_gruh[idx] = hn;
    g_outs[(size_t)t * BB * HH + idx] = hn;
}

// ------------------------- attention + prediction head -------------------------
__global__ void k_final(const float* __restrict__ attn_w, const float* __restrict__ attn_b,
                        const float* __restrict__ pw1, const float* __restrict__ pb1,
                        const float* __restrict__ pw2, const float* __restrict__ pb2,
                        float* __restrict__ out)
{
    int b = blockIdx.x;
    int j = threadIdx.x;                   // 128
    __shared__ float so[TT][HH];
    __shared__ float red[HH];
    __shared__ float sc[TT];
    __shared__ float w8[TT];
    __shared__ float hm[16];

#pragma unroll
    for (int t = 0; t < TT; t++) so[t][j] = g_outs[((size_t)t * BB + b) * HH + j];
    float aw = attn_w[j];
    __syncthreads();

    for (int t = 0; t < TT; t++) {
        red[j] = so[t][j] * aw;
        __syncthreads();
        for (int off = 64; off > 0; off >>= 1) {
            if (j < off) red[j] += red[j + off];
            __syncthreads();
        }
        if (j == 0) sc[t] = tanhf(red[0] + attn_b[0]);
        __syncthreads();
    }
    if (j == 0) {
        float mx = sc[0];
        for (int t = 1; t < TT; t++) mx = fmaxf(mx, sc[t]);
        float s = 0.f;
        for (int t = 0; t < TT; t++) { w8[t] = expf(sc[t] - mx); s += w8[t]; }
        float inv = 1.f / s;
        for (int t = 0; t < TT; t++) w8[t] *= inv;
    }
    __syncthreads();
    float rep = 0.f;
#pragma unroll
    for (int t = 0; t < TT; t++) rep = fmaf(w8[t], so[t][j], rep);
    red[j] = rep;
    __syncthreads();
    if (j < 16) {
        float s = pb1[j];
        for (int k = 0; k < HH; k++) s = fmaf(red[k], pw1[k * 16 + j], s);
        hm[j] = fmaxf(s, 0.f);
    }
    __syncthreads();
    if (j == 0) {
        float p = pb2[0];
#pragma unroll
        for (int k = 0; k < 16; k++) p = fmaf(hm[k], pw2[k], p);
        out[b] = p;
    }
    if (j < TT) out[BB + b * TT + j] = w8[j];
}

// ------------------------- launch -------------------------
extern "C" void kernel_launch(void* const* d_in, const int* in_sizes, int n_in,
                              void* d_out, int out_size)
{
    const float* x       = (const float*)d_in[0];
    const void*  ei      = d_in[1];
    const void*  ti      = d_in[2];
    const float* proj_w  = (const float*)d_in[3];
    const float* proj_b  = (const float*)d_in[4];
    const float* gcn_w1  = (const float*)d_in[5];
    const float* gcn_b1  = (const float*)d_in[6];
    const float* gcn_w2  = (const float*)d_in[7];
    const float* gcn_b2  = (const float*)d_in[8];
    const float* gru_w_ih = (const float*)d_in[9];
    const float* gru_w_hh = (const float*)d_in[10];
    const float* gru_b_ih = (const float*)d_in[11];
    const float* gru_b_hh = (const float*)d_in[12];
    const float* attn_w  = (const float*)d_in[13];
    const float* attn_b  = (const float*)d_in[14];
    const float* pred_w1 = (const float*)d_in[15];
    const float* pred_b1 = (const float*)d_in[16];
    const float* pred_w2 = (const float*)d_in[17];
    const float* pred_b2 = (const float*)d_in[18];
    float* out = (float*)d_out;

    dim3 gAll(1, (MALL + 127) / 128);            // 2500 blocks (proj, gemm1 upper bound)
    dim3 gG2(1, (TT * BB + 127) / 128);          // 64 blocks (gemm2 upper bound)
    dim3 gGi(3, (TT * BB + 127) / 128);
    dim3 gGru(3, (BB + 127) / 128);
    const int agg1Blocks = (MALL * 32 + 255) / 256;
    const int agg2Blocks = (TT * BB * 32 + 255) / 256;
    dim3 gGather(BB, TT);

    // index 3 = batched proj GEMM (ncu captures launch 3)
    k_detect<<<1, 1024>>>((const unsigned int*)ei, BB);                          // 0
    k_cvt_ti<<<(BB + 255) / 256, 256>>>(ti);                                     // 1
    k_cvt_edges<<<(NE + 255) / 256, 256>>>(ei);                                  // 2
    sgemm2<0, 0, 1, 0, true, true><<<gAll, 256>>>(x, proj_w, proj_b, MALL, PP, FF); // 3: proj ALL t
    k_transpose_wih<<<(384 * 256 + 255) / 256, 256>>>(gru_w_ih);                 // 4
    k_transpose_whh<<<(384 * 128 + 255) / 256, 256>>>(gru_w_hh);                 // 5

    // graph preprocessing
    k_init_deg<<<(NNODE + 255) / 256, 256>>>();
    k_deg_edges<<<(NE + 255) / 256, 256>>>();
    k_dinv<<<(NNODE + 255) / 256, 256>>>();
    k_scan<<<1, 1024>>>();
    k_selfloop<<<(NNODE + 255) / 256, 256>>>();
    k_fill_edges<<<(NE + 255) / 256, 256>>>();
    k_clear_masks<<<(NNODE + 255) / 256, 256>>>();
    k_mark_t<<<(BB + 255) / 256, 256>>>();
    k_mark_s<<<(NE + 255) / 256, 256>>>();
    k_mark_s2<<<(NNODE + 255) / 256, 256>>>();
    k_compact<<<(NNODE + 255) / 256, 256>>>();
    k_zero_h0<<<(BB * HH + 255) / 256, 256>>>();

    // GCN via linearity: agg first, GEMM on compact rows
    k_agg1_all<<<agg1Blocks, 256>>>();
    // h1c = relu(agg1 @ W1 + b1), M = 8*ns
    sgemm2<1, 0, 2, 1, true, true><<<gAll, 256>>>(nullptr, gcn_w1, gcn_b1, 0, GG, PP);
    k_agg2_all<<<agg2Blocks, 256>>>();
    // h2c = relu(agg2 @ W2 + b2), M = 8*nt
    sgemm2<2, 0, 3, 2, true, true><<<gG2, 256>>>(nullptr, gcn_w2, gcn_b2, 0, GG, GG);
    k_gather_all<<<gGather, 256>>>();

    // GI = tgt (8192 x 256) @ wihT + b_ih
    sgemm2<3, 1, 4, 0, false, true><<<gGi, 256>>>(nullptr, nullptr, gru_b_ih, TT * BB, 3 * HH, 2 * GG);

    for (int t = 0; t < TT; t++) {
        sgemm2<4, 2, 5, 0, false, true><<<gGru, 256>>>(nullptr, nullptr, gru_b_hh, BB, 3 * HH, HH);
        k_gru_pt<<<(BB * HH + 255) / 256, 256>>>(t);
    }

    k_final<<<BB, HH>>>(attn_w, attn_b, pred_w1, pred_b1, pred_w2, pred_b2, out);
}